// round 9
// baseline (speedup 1.0000x reference)
#include <cuda_runtime.h>
#include <cuda_bf16.h>

#define BATCH 4096
#define TLEN  2048
#define DIN   5
#define H1    9
#define H2    32
#define OUTL  25

// 2*log2(e): folded into stage-1/2 weights so tanh needs no pre-multiply.
#define C2L2E 2.8853900817779268f

#define MASK27 0x07FFFFFFu
#define NW1    1366          // stage-1 warps: 683 per direction, 6 seqs each

// Scratch for stage-1 result y = [h_f | h_b] per batch row.
__device__ float g_y[BATCH * 2 * H1];

#define FMA2(d, a, b, c) \
    asm("fma.rn.f32x2 %0, %1, %2, %3;" : "=l"(d) : "l"(a), "l"(b), "l"(c))
#define MUL2(d, a, b) \
    asm("mul.rn.f32x2 %0, %1, %2;" : "=l"(d) : "l"(a), "l"(b))
#define ADD2(d, a, b) \
    asm("add.rn.f32x2 %0, %1, %2;" : "=l"(d) : "l"(a), "l"(b))
#define PACK2(d, lo, hi) \
    asm("mov.b64 %0, {%1, %2};" : "=l"(d) : "r"(__float_as_uint(lo)), "r"(__float_as_uint(hi)))
#define UNPACK2(lo, hi, s) \
    asm("mov.b64 {%0, %1}, %2;" : "=r"(lo), "=r"(hi) : "l"(s))

// ---------------------------------------------------------------------------
// Stage 1: bidirectional Elman RNN over T=2048. Lane-per-neuron, 3 groups of
// 9 lanes per warp; each lane carries TWO sequences of the same direction
// packed as f32x2. State r = rcp(exp(z')+1) exchanged as float2 pairs via
// double-buffered smem; recurrent matvec uses fma.rn.f32x2 on LDS.128-loaded
// pairs. h = 1-2r folded into recurrent weights and bias.
// ---------------------------------------------------------------------------
__global__ __launch_bounds__(128) void rnn1_kernel(
    const float* __restrict__ x,
    const float* __restrict__ w_ih_f, const float* __restrict__ w_hh_f,
    const float* __restrict__ b_ih_f, const float* __restrict__ b_hh_f,
    const float* __restrict__ w_ih_b, const float* __restrict__ w_hh_b,
    const float* __restrict__ b_ih_b, const float* __restrict__ b_hh_b)
{
    __shared__ __align__(16) float hx[4][2][3][24];  // [warp][parity][group][12 pairs]

    const int lane = threadIdx.x & 31;
    if (lane >= 27) return;                       // 3 groups of 9 lanes
    const int wl   = threadIdx.x >> 5;
    const int warp = blockIdx.x * 4 + wl;
    if (warp >= NW1) return;

    const int g  = lane / 9;
    const int j  = lane - 9 * g;
    const int dir = (warp >= NW1 / 2) ? 1 : 0;       // 683 warps per dir
    const int wd  = warp - dir * (NW1 / 2);
    const int s0r = wd * 6 + 2 * g;                  // raw seq ids
    const int s1r = s0r + 1;
    const int s0  = (s0r < BATCH) ? s0r : (BATCH - 2);
    const int s1  = (s1r < BATCH) ? s1r : (BATCH - 1);
    const bool vA = (s0r < BATCH), vB = (s1r < BATCH);

    const float* wih_g = dir ? w_ih_b : w_ih_f;
    const float* whh_g = dir ? w_hh_b : w_hh_f;
    const float* bi_g  = dir ? b_ih_b : b_ih_f;
    const float* bh_g  = dir ? b_hh_b : b_hh_f;

    float wih[DIN];
    unsigned long long wp[H1];
    float wsum = 0.0f;
#pragma unroll
    for (int d = 0; d < DIN; d++) wih[d] = C2L2E * __ldg(wih_g + j * DIN + d);
#pragma unroll
    for (int k = 0; k < H1; k++) {
        float w = __ldg(whh_g + j * H1 + k);
        wsum += w;
        float wk = -2.0f * C2L2E * w;
        PACK2(wp[k], wk, wk);
    }
    const float bz2 = C2L2E * (__ldg(bi_g + j) + __ldg(bh_g + j) + wsum);
    float rA = 0.5f, rB = 0.5f;                     // h = 1-2r = 0

    float* sbase = &hx[wl][0][g][0];                // parity stride = 72 floats

    const float4* xqA = reinterpret_cast<const float4*>(x + (size_t)s0 * (TLEN * DIN));
    const float4* xqB = reinterpret_cast<const float4*>(x + (size_t)s1 * (TLEN * DIN));
    const int q0  = dir ? (TLEN / 4 - 1) * DIN : 0;   // 2555 or 0
    const int qdq = dir ? -DIN : DIN;

#define LOADCHUNK2(c, RA_, RB_) do {                                   \
        const float4* _pa = xqA + (q0 + (c) * qdq);                    \
        const float4* _pb = xqB + (q0 + (c) * qdq);                    \
        RA_[0] = __ldg(_pa + 0); RA_[1] = __ldg(_pa + 1);              \
        RA_[2] = __ldg(_pa + 2); RA_[3] = __ldg(_pa + 3);              \
        RA_[4] = __ldg(_pa + 4);                                       \
        RB_[0] = __ldg(_pb + 0); RB_[1] = __ldg(_pb + 1);              \
        RB_[2] = __ldg(_pb + 2); RB_[3] = __ldg(_pb + 3);              \
        RB_[4] = __ldg(_pb + 4);                                       \
    } while (0)

#define STEP(P, a0,a1,a2,a3,a4, b0,b1,b2,b3,b4) do {                   \
        reinterpret_cast<float2*>(sbase + (P) * 72)[j] = make_float2(rA, rB); \
        __syncwarp(MASK27);                                            \
        const float* fp = sbase + (P) * 72;                            \
        const ulonglong2 q01 = *reinterpret_cast<const ulonglong2*>(fp);      \
        const ulonglong2 q23 = *reinterpret_cast<const ulonglong2*>(fp + 4);  \
        const ulonglong2 q45 = *reinterpret_cast<const ulonglong2*>(fp + 8);  \
        const ulonglong2 q67 = *reinterpret_cast<const ulonglong2*>(fp + 12); \
        const unsigned long long q8 = *reinterpret_cast<const unsigned long long*>(fp + 16); \
        float zA = bz2, zB = bz2;                                      \
        zA = fmaf(wih[0], (a0), zA);  zB = fmaf(wih[0], (b0), zB);     \
        zA = fmaf(wih[1], (a1), zA);  zB = fmaf(wih[1], (b1), zB);     \
        zA = fmaf(wih[2], (a2), zA);  zB = fmaf(wih[2], (b2), zB);     \
        zA = fmaf(wih[3], (a3), zA);  zB = fmaf(wih[3], (b3), zB);     \
        zA = fmaf(wih[4], (a4), zA);  zB = fmaf(wih[4], (b4), zB);     \
        unsigned long long acc0, acc1;                                 \
        PACK2(acc0, zA, zB);                                           \
        FMA2(acc0, wp[0], q01.x, acc0);                                \
        MUL2(acc1, wp[1], q01.y);                                      \
        FMA2(acc0, wp[2], q23.x, acc0);                                \
        FMA2(acc1, wp[3], q23.y, acc1);                                \
        FMA2(acc0, wp[4], q45.x, acc0);                                \
        FMA2(acc1, wp[5], q45.y, acc1);                                \
        FMA2(acc0, wp[6], q67.x, acc0);                                \
        FMA2(acc1, wp[7], q67.y, acc1);                                \
        FMA2(acc0, wp[8], q8, acc0);                                   \
        ADD2(acc0, acc0, acc1);                                        \
        unsigned uA, uB;                                               \
        UNPACK2(uA, uB, acc0);                                         \
        float eA, eB;                                                  \
        asm("ex2.approx.f32 %0, %1;" : "=f"(eA) : "f"(__uint_as_float(uA))); \
        asm("ex2.approx.f32 %0, %1;" : "=f"(eB) : "f"(__uint_as_float(uB))); \
        asm("rcp.approx.f32 %0, %1;" : "=f"(rA) : "f"(eA + 1.0f));     \
        asm("rcp.approx.f32 %0, %1;" : "=f"(rB) : "f"(eB + 1.0f));     \
    } while (0)

#define CHUNK_FWD(RA_, RB_)                                                        \
        STEP(0, RA_[0].x,RA_[0].y,RA_[0].z,RA_[0].w,RA_[1].x,                      \
                RB_[0].x,RB_[0].y,RB_[0].z,RB_[0].w,RB_[1].x);                     \
        STEP(1, RA_[1].y,RA_[1].z,RA_[1].w,RA_[2].x,RA_[2].y,                      \
                RB_[1].y,RB_[1].z,RB_[1].w,RB_[2].x,RB_[2].y);                     \
        STEP(0, RA_[2].z,RA_[2].w,RA_[3].x,RA_[3].y,RA_[3].z,                      \
                RB_[2].z,RB_[2].w,RB_[3].x,RB_[3].y,RB_[3].z);                     \
        STEP(1, RA_[3].w,RA_[4].x,RA_[4].y,RA_[4].z,RA_[4].w,                      \
                RB_[3].w,RB_[4].x,RB_[4].y,RB_[4].z,RB_[4].w);

#define CHUNK_BWD(RA_, RB_)                                                        \
        STEP(0, RA_[3].w,RA_[4].x,RA_[4].y,RA_[4].z,RA_[4].w,                      \
                RB_[3].w,RB_[4].x,RB_[4].y,RB_[4].z,RB_[4].w);                     \
        STEP(1, RA_[2].z,RA_[2].w,RA_[3].x,RA_[3].y,RA_[3].z,                      \
                RB_[2].z,RB_[2].w,RB_[3].x,RB_[3].y,RB_[3].z);                     \
        STEP(0, RA_[1].y,RA_[1].z,RA_[1].w,RA_[2].x,RA_[2].y,                      \
                RB_[1].y,RB_[1].z,RB_[1].w,RB_[2].x,RB_[2].y);                     \
        STEP(1, RA_[0].x,RA_[0].y,RA_[0].z,RA_[0].w,RA_[1].x,                      \
                RB_[0].x,RB_[0].y,RB_[0].z,RB_[0].w,RB_[1].x);

    float4 XA[5], XB[5], YA[5], YB[5];
    LOADCHUNK2(0, XA, XB);
    const int NCHUNK = TLEN / 4;   // 512 (even)
    if (dir == 0) {
        for (int c = 0; c < NCHUNK; c += 2) {
            LOADCHUNK2(c + 1, YA, YB);
            CHUNK_FWD(XA, XB);
            if (c + 2 < NCHUNK) LOADCHUNK2(c + 2, XA, XB);
            CHUNK_FWD(YA, YB);
        }
    } else {
        for (int c = 0; c < NCHUNK; c += 2) {
            LOADCHUNK2(c + 1, YA, YB);
            CHUNK_BWD(XA, XB);
            if (c + 2 < NCHUNK) LOADCHUNK2(c + 2, XA, XB);
            CHUNK_BWD(YA, YB);
        }
    }

    if (vA) g_y[s0 * (2 * H1) + dir * H1 + j] = fmaf(-2.0f, rA, 1.0f);
    if (vB) g_y[s1 * (2 * H1) + dir * H1 + j] = fmaf(-2.0f, rB, 1.0f);
#undef LOADCHUNK2
#undef STEP
#undef CHUNK_FWD
#undef CHUNK_BWD
}

// ---------------------------------------------------------------------------
// Stage 2: 25-step RNN (input only at t=0) + linear 32->3.  (Proven R5 code.)
// One warp per batch row; lane j owns neuron j. State r exchanged via
// double-buffered smem; lanes 0-2 each own one output channel.
// ---------------------------------------------------------------------------
__global__ __launch_bounds__(256) void rnn2_kernel(
    const float* __restrict__ w_ih2, const float* __restrict__ w_hh2,
    const float* __restrict__ b_ih2, const float* __restrict__ b_hh2,
    const float* __restrict__ w_out, const float* __restrict__ b_out,
    float* __restrict__ out)
{
    __shared__ __align__(16) float rbuf[8][2][H2];   // [warp][parity][32]

    const int gtid = blockIdx.x * blockDim.x + threadIdx.x;
    const int b  = gtid >> 5;
    const int j  = gtid & 31;
    const int wl = (threadIdx.x >> 5);

    float wh2[H2];
    float wsum = 0.0f;
#pragma unroll
    for (int k = 0; k < H2; k++) {
        float w = __ldg(w_hh2 + j * H2 + k);
        wsum += w;
        wh2[k] = -2.0f * C2L2E * w;
    }
    const float bin = C2L2E * (__ldg(b_ih2 + j) + __ldg(b_hh2 + j));
    const float bz  = bin + C2L2E * wsum;

    const int oc = (j < 3) ? j : 0;
    float wor[H2];
    float osum = 0.0f;
#pragma unroll
    for (int k = 0; k < H2; k++) {
        float w = __ldg(w_out + oc * H2 + k);
        osum += w;
        wor[k] = -2.0f * w;
    }
    const float oconst = osum + __ldg(b_out + oc);

    float* sb = &rbuf[wl][0][0];                 // parity stride = 32 floats

    // ---- Step 0: h = tanh(W_ih2 @ y + b). Broadcast y via smem.
    sb[j] = (j < 2 * H1) ? g_y[b * (2 * H1) + j] : 0.0f;
    __syncwarp();
    float r;
    {
        const float4 y0 = *reinterpret_cast<const float4*>(sb + 0);
        const float4 y1 = *reinterpret_cast<const float4*>(sb + 4);
        const float4 y2 = *reinterpret_cast<const float4*>(sb + 8);
        const float4 y3 = *reinterpret_cast<const float4*>(sb + 12);
        const float  y16 = sb[16], y17 = sb[17];
        float za = bin, zb = 0.0f;
        const float* wi = w_ih2 + j * (2 * H1);
        za = fmaf(C2L2E * __ldg(wi + 0),  y0.x, za);
        zb = fmaf(C2L2E * __ldg(wi + 1),  y0.y, zb);
        za = fmaf(C2L2E * __ldg(wi + 2),  y0.z, za);
        zb = fmaf(C2L2E * __ldg(wi + 3),  y0.w, zb);
        za = fmaf(C2L2E * __ldg(wi + 4),  y1.x, za);
        zb = fmaf(C2L2E * __ldg(wi + 5),  y1.y, zb);
        za = fmaf(C2L2E * __ldg(wi + 6),  y1.z, za);
        zb = fmaf(C2L2E * __ldg(wi + 7),  y1.w, zb);
        za = fmaf(C2L2E * __ldg(wi + 8),  y2.x, za);
        zb = fmaf(C2L2E * __ldg(wi + 9),  y2.y, zb);
        za = fmaf(C2L2E * __ldg(wi + 10), y2.z, za);
        zb = fmaf(C2L2E * __ldg(wi + 11), y2.w, zb);
        za = fmaf(C2L2E * __ldg(wi + 12), y3.x, za);
        zb = fmaf(C2L2E * __ldg(wi + 13), y3.y, zb);
        za = fmaf(C2L2E * __ldg(wi + 14), y3.z, za);
        zb = fmaf(C2L2E * __ldg(wi + 15), y3.w, zb);
        za = fmaf(C2L2E * __ldg(wi + 16), y16, za);
        zb = fmaf(C2L2E * __ldg(wi + 17), y17, zb);
        float e;
        asm("ex2.approx.f32 %0, %1;" : "=f"(e) : "f"(za + zb));
        asm("rcp.approx.f32 %0, %1;" : "=f"(r) : "f"(e + 1.0f));
    }

    float* ob = out + (size_t)b * OUTL * 3;
    int p = 0;

    for (int t = 0; t < OUTL; t++) {
        sb[p * H2 + j] = r;
        __syncwarp();
        float rv[H2];
#pragma unroll
        for (int q = 0; q < H2; q += 4) {
            const float4 v = *reinterpret_cast<const float4*>(sb + p * H2 + q);
            rv[q] = v.x; rv[q + 1] = v.y; rv[q + 2] = v.z; rv[q + 3] = v.w;
        }

        float s0 = oconst, s1 = 0.f, s2 = 0.f, s3 = 0.f;
#pragma unroll
        for (int k = 0; k < H2; k += 4) {
            s0 = fmaf(wor[k],     rv[k],     s0);
            s1 = fmaf(wor[k + 1], rv[k + 1], s1);
            s2 = fmaf(wor[k + 2], rv[k + 2], s2);
            s3 = fmaf(wor[k + 3], rv[k + 3], s3);
        }
        if (j < 3) ob[t * 3 + j] = (s0 + s1) + (s2 + s3);

        if (t < OUTL - 1) {
            float q0 = bz, q1 = 0.f, q2 = 0.f, q3 = 0.f;
#pragma unroll
            for (int k = 0; k < H2; k += 4) {
                q0 = fmaf(wh2[k],     rv[k],     q0);
                q1 = fmaf(wh2[k + 1], rv[k + 1], q1);
                q2 = fmaf(wh2[k + 2], rv[k + 2], q2);
                q3 = fmaf(wh2[k + 3], rv[k + 3], q3);
            }
            float e;
            asm("ex2.approx.f32 %0, %1;" : "=f"(e) : "f"((q0 + q1) + (q2 + q3)));
            asm("rcp.approx.f32 %0, %1;" : "=f"(r) : "f"(e + 1.0f));
        }
        p ^= 1;
    }
}

extern "C" void kernel_launch(void* const* d_in, const int* in_sizes, int n_in,
                              void* d_out, int out_size)
{
    const float* x      = (const float*)d_in[0];
    const float* w_ih_f = (const float*)d_in[1];
    const float* w_hh_f = (const float*)d_in[2];
    const float* b_ih_f = (const float*)d_in[3];
    const float* b_hh_f = (const float*)d_in[4];
    const float* w_ih_b = (const float*)d_in[5];
    const float* w_hh_b = (const float*)d_in[6];
    const float* b_ih_b = (const float*)d_in[7];
    const float* b_hh_b = (const float*)d_in[8];
    const float* w_ih2  = (const float*)d_in[9];
    const float* w_hh2  = (const float*)d_in[10];
    const float* b_ih2  = (const float*)d_in[11];
    const float* b_hh2  = (const float*)d_in[12];
    const float* w_out  = (const float*)d_in[13];
    const float* b_out  = (const float*)d_in[14];
    float* out = (float*)d_out;

    // Stage 1: 1366 warps (683 per direction, 6 seqs each), 4 warps/block.
    rnn1_kernel<<<(NW1 + 3) / 4, 128>>>(x, w_ih_f, w_hh_f, b_ih_f, b_hh_f,
                                        w_ih_b, w_hh_b, b_ih_b, b_hh_b);

    // Stage 2: warp per batch row.
    rnn2_kernel<<<(BATCH * 32) / 256, 256>>>(w_ih2, w_hh2, b_ih2, b_hh2,
                                             w_out, b_out, out);
}